// round 2
// baseline (speedup 1.0000x reference)
#include <cuda_runtime.h>
#include <cuda_fp16.h>
#include <cstdint>
#include <cstddef>

// Problem dims (fixed by the reference)
static constexpr int M_DIM  = 512;    // B*S
static constexpr int K_DIM  = 4096;   // IN
static constexpr int N_DIM  = 11008;  // OUT
static constexpr int MTILE  = 128;
static constexpr int NTILE  = 128;
static constexpr int KSLAB  = 64;     // K per pipeline slab
static constexpr int NSLABS = K_DIM / KSLAB;   // 64
static constexpr int THREADS = 256;

// fp16 copy of the activations (exact GEMM except one f32->f16 rounding)
__device__ __half g_A[M_DIM * K_DIM];   // 4 MB static scratch

// ------------------------------------------------------------------ helpers
__device__ __forceinline__ uint32_t smem_u32(const void* p) {
    uint32_t r;
    asm("{ .reg .u64 t; cvta.to.shared.u64 t, %1; cvt.u32.u64 %0, t; }"
        : "=r"(r) : "l"(p));
    return r;
}

// XOR swizzle on 128B rows (16B chunks) -> conflict-free ldmatrix
#define SWZ(o) ((o) ^ (((o) >> 3) & 0x70))

__device__ __forceinline__ void ldsm_x4(uint32_t& r0, uint32_t& r1,
                                        uint32_t& r2, uint32_t& r3, uint32_t a) {
    asm volatile("ldmatrix.sync.aligned.m8n8.x4.shared.b16 {%0,%1,%2,%3}, [%4];"
                 : "=r"(r0), "=r"(r1), "=r"(r2), "=r"(r3) : "r"(a));
}

__device__ __forceinline__ void mma16816(float* d, const uint32_t* a,
                                         uint32_t b0, uint32_t b1) {
    asm volatile(
        "mma.sync.aligned.m16n8k16.row.col.f32.f16.f16.f32 "
        "{%0,%1,%2,%3}, {%4,%5,%6,%7}, {%8,%9}, {%0,%1,%2,%3};"
        : "+f"(d[0]), "+f"(d[1]), "+f"(d[2]), "+f"(d[3])
        : "r"(a[0]), "r"(a[1]), "r"(a[2]), "r"(a[3]), "r"(b0), "r"(b1));
}

// ------------------------------------------------------------------ SMEM layout
// stage p at p*32768: A tile (128 rows x 128B) then W tile (128 rows x 128B)
static constexpr int STAGE_BYTES = 32768;
static constexpr int W_OFF       = 16384;
static constexpr int SMEM_BYTES  = 2 * STAGE_BYTES + 1024;  // + align slack

// ------------------------------------------------------------------ kernels
__global__ void convert_A_kernel(const float* __restrict__ in) {
    int n4 = (M_DIM * K_DIM) / 4;
    int i = blockIdx.x * blockDim.x + threadIdx.x;
    if (i >= n4) return;
    float4 v = reinterpret_cast<const float4*>(in)[i];
    __half2 h0 = __floats2half2_rn(v.x, v.y);
    __half2 h1 = __floats2half2_rn(v.z, v.w);
    uint2 u;
    u.x = *reinterpret_cast<uint32_t*>(&h0);
    u.y = *reinterpret_cast<uint32_t*>(&h1);
    reinterpret_cast<uint2*>(g_A)[i] = u;
}

__global__ void __launch_bounds__(THREADS, 1)
qlinear_hmma_kernel(const int4* __restrict__ W, const float* __restrict__ scale,
                    const float* __restrict__ bias, float* __restrict__ out) {
    extern __shared__ char smem_raw[];
    const uint32_t smem = (smem_u32(smem_raw) + 1023u) & ~1023u;

    const int tid  = threadIdx.x;
    const int wid  = tid >> 5;
    const int lane = tid & 31;
    const int wm   = wid >> 2;          // 0..1 : 64-row M strip
    const int wn   = wid & 3;           // 0..3 : 32-col N strip
    const int m0   = blockIdx.x * MTILE;    // m fastest -> weight L2 reuse
    const int n0   = blockIdx.y * NTILE;

    const __half* Abase = g_A + (size_t)m0 * K_DIM;
    const size_t  wrow  = (size_t)K_DIM / 4;   // int32s per weight row / 4

    float acc[4][4][4];
#pragma unroll
    for (int i = 0; i < 4; i++)
#pragma unroll
        for (int j = 0; j < 4; j++)
#pragma unroll
            for (int e = 0; e < 4; e++) acc[i][j][e] = 0.f;

    // per-thread W staging (regs reused every slab)
    int4 wq[8];

    // ---- prologue: W(0) -> regs, A(0) -> smem stage 0 -------------------
#pragma unroll
    for (int i = 0; i < 8; i++) {
        int li = i * 256 + tid, r = li >> 4, cg = li & 15;
        wq[i] = W[(size_t)(n0 + r) * wrow + 0 * (KSLAB / 4) + cg];
    }
#pragma unroll
    for (int i = 0; i < 4; i++) {
        int li = i * 256 + tid, r = li >> 3, c = li & 7;
        const __half* src = Abase + (size_t)r * K_DIM + c * 8;
        uint32_t dst = smem + SWZ(r * 128 + c * 16);
        asm volatile("cp.async.cg.shared.global [%0], [%1], 16;" :: "r"(dst), "l"(src));
    }
    asm volatile("cp.async.commit_group;" ::: "memory");

    // ---- main loop ------------------------------------------------------
#pragma unroll 1
    for (int s = 0; s < NSLABS; s++) {
        const int p = s & 1;
        const uint32_t a_sm = smem + p * STAGE_BYTES;
        const uint32_t w_sm = a_sm + W_OFF;

        // dequant W(s): exact (q-128) in fp16 -> STS
#pragma unroll
        for (int i = 0; i < 8; i++) {
            int li = i * 256 + tid, r = li >> 4, cg = li & 15;
            __half2 h0 = __halves2half2(__int2half_rn(wq[i].x - 128),
                                        __int2half_rn(wq[i].y - 128));
            __half2 h1 = __halves2half2(__int2half_rn(wq[i].z - 128),
                                        __int2half_rn(wq[i].w - 128));
            uint32_t u0 = *reinterpret_cast<uint32_t*>(&h0);
            uint32_t u1 = *reinterpret_cast<uint32_t*>(&h1);
            uint32_t dst = w_sm + SWZ(r * 128 + cg * 8);
            asm volatile("st.shared.v2.b32 [%0], {%1, %2};"
                         :: "r"(dst), "r"(u0), "r"(u1) : "memory");
        }

        asm volatile("cp.async.wait_group 0;" ::: "memory");   // A(s) arrived
        __syncthreads();                                       // stage p ready

        // prefetch next slab (overlaps compute below)
        if (s + 1 < NSLABS) {
#pragma unroll
            for (int i = 0; i < 8; i++) {
                int li = i * 256 + tid, r = li >> 4, cg = li & 15;
                wq[i] = W[(size_t)(n0 + r) * wrow + (s + 1) * (KSLAB / 4) + cg];
            }
#pragma unroll
            for (int i = 0; i < 4; i++) {
                int li = i * 256 + tid, r = li >> 3, c = li & 7;
                const __half* src = Abase + (size_t)r * K_DIM + (s + 1) * KSLAB + c * 8;
                uint32_t dst = smem + (p ^ 1) * STAGE_BYTES + SWZ(r * 128 + c * 16);
                asm volatile("cp.async.cg.shared.global [%0], [%1], 16;"
                             :: "r"(dst), "l"(src));
            }
            asm volatile("cp.async.commit_group;" ::: "memory");
        }

        // compute slab s: 4 k-steps of 16
#pragma unroll
        for (int ks = 0; ks < 4; ks++) {
            const int chunk = ks * 2 + (lane >> 4);
            uint32_t a[4][4];
#pragma unroll
            for (int mt = 0; mt < 4; mt++) {
                int row = wm * 64 + mt * 16 + (lane & 15);
                ldsm_x4(a[mt][0], a[mt][1], a[mt][2], a[mt][3],
                        a_sm + SWZ(row * 128 + chunk * 16));
            }
            uint32_t b[4][2];
#pragma unroll
            for (int j = 0; j < 2; j++) {
                int row = wn * 32 + j * 16 + (lane & 15);
                uint32_t t0, t1, t2, t3;
                ldsm_x4(t0, t1, t2, t3, w_sm + SWZ(row * 128 + chunk * 16));
                b[j * 2 + 0][0] = t0;  b[j * 2 + 1][0] = t1;
                b[j * 2 + 0][1] = t2;  b[j * 2 + 1][1] = t3;
            }
#pragma unroll
            for (int mt = 0; mt < 4; mt++)
#pragma unroll
                for (int nt = 0; nt < 4; nt++)
                    mma16816(acc[mt][nt], a[mt], b[nt][0], b[nt][1]);
        }
    }

    // ---- epilogue: scale*acc + bias -> out ------------------------------
    const int ncb = n0 + wn * 32;
    float sc[4][2], bs[4][2];
#pragma unroll
    for (int nt = 0; nt < 4; nt++) {
#pragma unroll
        for (int e = 0; e < 2; e++) {
            int col = ncb + nt * 8 + (lane & 3) * 2 + e;
            sc[nt][e] = __ldg(&scale[col]);
            bs[nt][e] = __ldg(&bias[col]);
        }
    }
#pragma unroll
    for (int mt = 0; mt < 4; mt++) {
        int row = m0 + wm * 64 + mt * 16 + (lane >> 2);
#pragma unroll
        for (int nt = 0; nt < 4; nt++) {
            int col = ncb + nt * 8 + (lane & 3) * 2;
            float2 v0, v1;
            v0.x = acc[mt][nt][0] * sc[nt][0] + bs[nt][0];
            v0.y = acc[mt][nt][1] * sc[nt][1] + bs[nt][1];
            v1.x = acc[mt][nt][2] * sc[nt][0] + bs[nt][0];
            v1.y = acc[mt][nt][3] * sc[nt][1] + bs[nt][1];
            *reinterpret_cast<float2*>(out + (size_t)row * N_DIM + col)       = v0;
            *reinterpret_cast<float2*>(out + (size_t)(row + 8) * N_DIM + col) = v1;
        }
    }
}

// ------------------------------------------------------------------ launch
extern "C" void kernel_launch(void* const* d_in, const int* in_sizes, int n_in,
                              void* d_out, int out_size) {
    (void)in_sizes; (void)n_in; (void)out_size;
    const float* input = (const float*)d_in[0];
    const int4*  W     = (const int4*)d_in[1];
    const float* scale = (const float*)d_in[2];
    const float* bias  = (const float*)d_in[3];
    float* out = (float*)d_out;

    convert_A_kernel<<<(M_DIM * K_DIM / 4 + 255) / 256, 256>>>(input);

    cudaFuncSetAttribute(qlinear_hmma_kernel,
                         cudaFuncAttributeMaxDynamicSharedMemorySize, SMEM_BYTES);
    dim3 grid(M_DIM / MTILE, N_DIM / NTILE);   // m fastest: weight L2 reuse
    qlinear_hmma_kernel<<<grid, THREADS, SMEM_BYTES>>>(W, scale, bias, out);
}

// round 3
// speedup vs baseline: 1.0187x; 1.0187x over previous
#include <cuda_runtime.h>
#include <cuda_fp16.h>
#include <cstdint>
#include <cstddef>

// Problem dims (fixed by the reference)
static constexpr int M_DIM  = 512;    // B*S
static constexpr int K_DIM  = 4096;   // IN
static constexpr int N_DIM  = 11008;  // OUT
static constexpr int MTILE  = 128;
static constexpr int NTILE  = 128;
static constexpr int KSLAB  = 64;     // K per pipeline slab
static constexpr int NSLABS = K_DIM / KSLAB;   // 64
static constexpr int THREADS = 512;   // 16 warps: 4(m) x 4(n), 32x32 each

// fp16 copy of the activations (exact GEMM except one f32->f16 rounding)
__device__ __half g_A[M_DIM * K_DIM];   // 4 MB static scratch

// ------------------------------------------------------------------ helpers
__device__ __forceinline__ uint32_t smem_u32(const void* p) {
    uint32_t r;
    asm("{ .reg .u64 t; cvta.to.shared.u64 t, %1; cvt.u32.u64 %0, t; }"
        : "=r"(r) : "l"(p));
    return r;
}

// XOR swizzle on 128B rows (16B chunks) -> conflict-free ldmatrix
#define SWZ(o) ((o) ^ (((o) >> 3) & 0x70))

__device__ __forceinline__ void ldsm_x4(uint32_t& r0, uint32_t& r1,
                                        uint32_t& r2, uint32_t& r3, uint32_t a) {
    asm volatile("ldmatrix.sync.aligned.m8n8.x4.shared.b16 {%0,%1,%2,%3}, [%4];"
                 : "=r"(r0), "=r"(r1), "=r"(r2), "=r"(r3) : "r"(a));
}

__device__ __forceinline__ void mma16816(float* d, const uint32_t* a,
                                         uint32_t b0, uint32_t b1) {
    asm volatile(
        "mma.sync.aligned.m16n8k16.row.col.f32.f16.f16.f32 "
        "{%0,%1,%2,%3}, {%4,%5,%6,%7}, {%8,%9}, {%0,%1,%2,%3};"
        : "+f"(d[0]), "+f"(d[1]), "+f"(d[2]), "+f"(d[3])
        : "r"(a[0]), "r"(a[1]), "r"(a[2]), "r"(a[3]), "r"(b0), "r"(b1));
}

// ------------------------------------------------------------------ SMEM layout
// stage p at p*32768: A tile (128 rows x 128B) then W tile (128 rows x 128B)
static constexpr int STAGE_BYTES = 32768;
static constexpr int W_OFF       = 16384;
static constexpr int SMEM_BYTES  = 2 * STAGE_BYTES + 1024;  // + align slack

// ------------------------------------------------------------------ kernels
__global__ void convert_A_kernel(const float* __restrict__ in) {
    int n4 = (M_DIM * K_DIM) / 4;
    int i = blockIdx.x * blockDim.x + threadIdx.x;
    if (i >= n4) return;
    float4 v = reinterpret_cast<const float4*>(in)[i];
    __half2 h0 = __floats2half2_rn(v.x, v.y);
    __half2 h1 = __floats2half2_rn(v.z, v.w);
    uint2 u;
    u.x = *reinterpret_cast<uint32_t*>(&h0);
    u.y = *reinterpret_cast<uint32_t*>(&h1);
    reinterpret_cast<uint2*>(g_A)[i] = u;
}

__global__ void __launch_bounds__(THREADS, 1)
qlinear_hmma_kernel(const int4* __restrict__ W, const float* __restrict__ scale,
                    const float* __restrict__ bias, float* __restrict__ out) {
    extern __shared__ char smem_raw[];
    const uint32_t smem = (smem_u32(smem_raw) + 1023u) & ~1023u;

    const int tid  = threadIdx.x;
    const int wid  = tid >> 5;
    const int lane = tid & 31;
    const int wm   = wid >> 2;          // 0..3 : 32-row M strip
    const int wn   = wid & 3;           // 0..3 : 32-col N strip
    const int m0   = blockIdx.x * MTILE;    // m fastest -> weight L2 reuse
    const int n0   = blockIdx.y * NTILE;

    const __half* Abase = g_A + (size_t)m0 * K_DIM;
    const size_t  wrow  = (size_t)K_DIM / 4;   // int4s per weight row

    float acc[2][4][4];
#pragma unroll
    for (int i = 0; i < 2; i++)
#pragma unroll
        for (int j = 0; j < 4; j++)
#pragma unroll
            for (int e = 0; e < 4; e++) acc[i][j][e] = 0.f;

    // per-thread W staging (regs reused every slab)
    int4 wq[4];

    // ---- prologue: W(0) -> regs, A(0) -> smem stage 0 -------------------
#pragma unroll
    for (int i = 0; i < 4; i++) {
        int li = i * 512 + tid, r = li >> 4, cg = li & 15;
        wq[i] = W[(size_t)(n0 + r) * wrow + cg];
    }
#pragma unroll
    for (int i = 0; i < 2; i++) {
        int li = i * 512 + tid, r = li >> 3, c = li & 7;
        const __half* src = Abase + (size_t)r * K_DIM + c * 8;
        uint32_t dst = smem + SWZ(r * 128 + c * 16);
        asm volatile("cp.async.cg.shared.global [%0], [%1], 16;" :: "r"(dst), "l"(src));
    }
    asm volatile("cp.async.commit_group;" ::: "memory");

    // ---- main loop ------------------------------------------------------
#pragma unroll 1
    for (int s = 0; s < NSLABS; s++) {
        const int p = s & 1;
        const uint32_t a_sm = smem + p * STAGE_BYTES;
        const uint32_t w_sm = a_sm + W_OFF;

        // dequant W(s): exact (q-128) in fp16 -> STS
#pragma unroll
        for (int i = 0; i < 4; i++) {
            int li = i * 512 + tid, r = li >> 4, cg = li & 15;
            __half2 h0 = __halves2half2(__int2half_rn(wq[i].x - 128),
                                        __int2half_rn(wq[i].y - 128));
            __half2 h1 = __halves2half2(__int2half_rn(wq[i].z - 128),
                                        __int2half_rn(wq[i].w - 128));
            uint32_t u0 = *reinterpret_cast<uint32_t*>(&h0);
            uint32_t u1 = *reinterpret_cast<uint32_t*>(&h1);
            uint32_t dst = w_sm + SWZ(r * 128 + cg * 8);
            asm volatile("st.shared.v2.b32 [%0], {%1, %2};"
                         :: "r"(dst), "r"(u0), "r"(u1) : "memory");
        }

        asm volatile("cp.async.wait_group 0;" ::: "memory");   // A(s) arrived
        __syncthreads();                                       // stage p ready

        // prefetch next slab (overlaps compute below)
        if (s + 1 < NSLABS) {
#pragma unroll
            for (int i = 0; i < 4; i++) {
                int li = i * 512 + tid, r = li >> 4, cg = li & 15;
                wq[i] = W[(size_t)(n0 + r) * wrow + (s + 1) * (KSLAB / 4) + cg];
            }
#pragma unroll
            for (int i = 0; i < 2; i++) {
                int li = i * 512 + tid, r = li >> 3, c = li & 7;
                const __half* src = Abase + (size_t)r * K_DIM + (s + 1) * KSLAB + c * 8;
                uint32_t dst = smem + (p ^ 1) * STAGE_BYTES + SWZ(r * 128 + c * 16);
                asm volatile("cp.async.cg.shared.global [%0], [%1], 16;"
                             :: "r"(dst), "l"(src));
            }
            asm volatile("cp.async.commit_group;" ::: "memory");
        }

        // compute slab s: 4 k-steps of 16
#pragma unroll
        for (int ks = 0; ks < 4; ks++) {
            const int chunk = ks * 2 + (lane >> 4);
            uint32_t a[2][4];
#pragma unroll
            for (int mt = 0; mt < 2; mt++) {
                int row = wm * 32 + mt * 16 + (lane & 15);
                ldsm_x4(a[mt][0], a[mt][1], a[mt][2], a[mt][3],
                        a_sm + SWZ(row * 128 + chunk * 16));
            }
            uint32_t b[4][2];
#pragma unroll
            for (int j = 0; j < 2; j++) {
                int row = wn * 32 + j * 16 + (lane & 15);
                uint32_t t0, t1, t2, t3;
                ldsm_x4(t0, t1, t2, t3, w_sm + SWZ(row * 128 + chunk * 16));
                b[j * 2 + 0][0] = t0;  b[j * 2 + 1][0] = t1;
                b[j * 2 + 0][1] = t2;  b[j * 2 + 1][1] = t3;
            }
#pragma unroll
            for (int mt = 0; mt < 2; mt++)
#pragma unroll
                for (int nt = 0; nt < 4; nt++)
                    mma16816(acc[mt][nt], a[mt], b[nt][0], b[nt][1]);
        }
    }

    // ---- epilogue: scale*acc + bias -> out ------------------------------
    const int ncb = n0 + wn * 32;
    float sc[4][2], bs[4][2];
#pragma unroll
    for (int nt = 0; nt < 4; nt++) {
#pragma unroll
        for (int e = 0; e < 2; e++) {
            int col = ncb + nt * 8 + (lane & 3) * 2 + e;
            sc[nt][e] = __ldg(&scale[col]);
            bs[nt][e] = __ldg(&bias[col]);
        }
    }
#pragma unroll
    for (int mt = 0; mt < 2; mt++) {
        int row = m0 + wm * 32 + mt * 16 + (lane >> 2);
#pragma unroll
        for (int nt = 0; nt < 4; nt++) {
            int col = ncb + nt * 8 + (lane & 3) * 2;
            float2 v0, v1;
            v0.x = acc[mt][nt][0] * sc[nt][0] + bs[nt][0];
            v0.y = acc[mt][nt][1] * sc[nt][1] + bs[nt][1];
            v1.x = acc[mt][nt][2] * sc[nt][0] + bs[nt][0];
            v1.y = acc[mt][nt][3] * sc[nt][1] + bs[nt][1];
            *reinterpret_cast<float2*>(out + (size_t)row * N_DIM + col)       = v0;
            *reinterpret_cast<float2*>(out + (size_t)(row + 8) * N_DIM + col) = v1;
        }
    }
}

// ------------------------------------------------------------------ launch
extern "C" void kernel_launch(void* const* d_in, const int* in_sizes, int n_in,
                              void* d_out, int out_size) {
    (void)in_sizes; (void)n_in; (void)out_size;
    const float* input = (const float*)d_in[0];
    const int4*  W     = (const int4*)d_in[1];
    const float* scale = (const float*)d_in[2];
    const float* bias  = (const float*)d_in[3];
    float* out = (float*)d_out;

    convert_A_kernel<<<(M_DIM * K_DIM / 4 + 255) / 256, 256>>>(input);

    cudaFuncSetAttribute(qlinear_hmma_kernel,
                         cudaFuncAttributeMaxDynamicSharedMemorySize, SMEM_BYTES);
    dim3 grid(M_DIM / MTILE, N_DIM / NTILE);   // m fastest: weight L2 reuse
    qlinear_hmma_kernel<<<grid, THREADS, SMEM_BYTES>>>(W, scale, bias, out);
}